// round 2
// baseline (speedup 1.0000x reference)
#include <cuda_runtime.h>

// CostVolume: out[b, o, y, x] = leaky( mean_c( c1[b,c,y,x] * warped[b,c,y+dy-4,x+dx-4] ) )
// Shapes: B=8, C=192, H=128, W=160, 81 offsets.
// Round 2: 2 x-pixels per thread, LDS.64 window loads (10-wide union row serves both
// pixels' 9-wide windows), 64-thread blocks for wave balance / occupancy.

#define SR 4
#define NOFF 81
#define C_TOTAL 192
#define H_TOTAL 128
#define W_TOTAL 160
#define B_TOTAL 8

#define TW 32        // tile width (pixels)
#define TH 4         // tile height (pixels)
#define NPAIR 16     // x-pairs per row
#define NTHREADS 64  // NPAIR * TH
#define CC 8         // channels per staged chunk
#define HW 40        // halo width  (TW + 2*SR)
#define HH 12        // halo height (TH + 2*SR)

__global__ __launch_bounds__(NTHREADS, 5)
void costvol_kernel(const float* __restrict__ c1,
                    const float* __restrict__ warped,
                    const float* __restrict__ alpha,
                    float* __restrict__ out) {
    __shared__ float s_c1[CC][TH][TW];     // 4 KB
    __shared__ float s_w[CC][HH][HW];      // 15 KB

    const int tid = threadIdx.x;
    const int p   = tid & (NPAIR - 1);     // x-pair index 0..15
    const int ty  = tid >> 4;              // row 0..3
    const int tx0 = p * 2;                 // even -> 8B-aligned smem accesses
    const int x0 = blockIdx.x * TW;
    const int y0 = blockIdx.y * TH;
    const int b  = blockIdx.z;

    const float av = __ldg(alpha);

    float acc0[NOFF], acc1[NOFF];
    #pragma unroll
    for (int i = 0; i < NOFF; i++) { acc0[i] = 0.f; acc1[i] = 0.f; }

    const size_t plane = (size_t)H_TOTAL * W_TOTAL;
    const float* c1b = c1     + (size_t)b * C_TOTAL * plane;
    const float* wb  = warped + (size_t)b * C_TOTAL * plane;

    #pragma unroll 1
    for (int cc = 0; cc < C_TOTAL; cc += CC) {
        // ---- stage c1 tile: CC*TH*TW = 1024 floats = 256 float4, 4 per thread ----
        #pragma unroll
        for (int i = 0; i < 4; i++) {
            int idx = tid + i * NTHREADS;   // float4 index 0..255
            int c   = idx >> 5;             // 32 float4 per channel
            int rem = idx & 31;
            int yy  = rem >> 3;
            int xx  = (rem & 7) * 4;
            float4 v = *(const float4*)(c1b + (size_t)(cc + c) * plane
                                        + (size_t)(y0 + yy) * W_TOTAL + (x0 + xx));
            *(float4*)&s_c1[c][yy][xx] = v;
        }
        // ---- stage warped halo: CC*HH*HW = 3840 floats ----
        #pragma unroll
        for (int c = 0; c < CC; c++) {
            const float* wc = wb + (size_t)(cc + c) * plane;
            #pragma unroll 1
            for (int j = tid; j < HH * HW; j += NTHREADS) {
                int yy = j / HW;
                int xx = j - yy * HW;
                int gy = y0 + yy - SR;
                int gx = x0 + xx - SR;
                float v = 0.f;
                if (gy >= 0 && gy < H_TOTAL && gx >= 0 && gx < W_TOTAL)
                    v = __ldg(wc + (size_t)gy * W_TOTAL + gx);
                s_w[c][yy][xx] = v;
            }
        }
        __syncthreads();

        // ---- accumulate: per channel, 46 LDS.64 feed 162 FFMA ----
        #pragma unroll 2
        for (int c = 0; c < CC; c++) {
            const float2 a2 = *(const float2*)&s_c1[c][ty][tx0];
            #pragma unroll
            for (int dy = 0; dy < 9; dy++) {
                const float2* wr = (const float2*)&s_w[c][ty + dy][tx0];
                float2 v0 = wr[0], v1 = wr[1], v2 = wr[2], v3 = wr[3], v4 = wr[4];
                float row[10] = {v0.x, v0.y, v1.x, v1.y, v2.x,
                                 v2.y, v3.x, v3.y, v4.x, v4.y};
                #pragma unroll
                for (int dx = 0; dx < 9; dx++) {
                    acc0[dy * 9 + dx] = fmaf(a2.x, row[dx],     acc0[dy * 9 + dx]);
                    acc1[dy * 9 + dx] = fmaf(a2.y, row[dx + 1], acc1[dy * 9 + dx]);
                }
            }
        }
        __syncthreads();
    }

    // ---- epilogue: mean over C, leaky-relu, vectorized store ----
    const float inv = 1.0f / (float)C_TOTAL;
    float* ob = out + (size_t)b * NOFF * plane
                    + (size_t)(y0 + ty) * W_TOTAL + (x0 + tx0);
    #pragma unroll
    for (int o = 0; o < NOFF; o++) {
        float r0 = acc0[o] * inv;
        float r1 = acc1[o] * inv;
        float2 v;
        v.x = (r0 >= 0.f) ? r0 : av * r0;
        v.y = (r1 >= 0.f) ? r1 : av * r1;
        *(float2*)(ob + (size_t)o * plane) = v;
    }
}

extern "C" void kernel_launch(void* const* d_in, const int* in_sizes, int n_in,
                              void* d_out, int out_size) {
    const float* c1     = (const float*)d_in[0];
    const float* warped = (const float*)d_in[1];
    const float* alpha  = (const float*)d_in[2];
    float* out          = (float*)d_out;

    dim3 grid(W_TOTAL / TW, H_TOTAL / TH, B_TOTAL);  // (5, 32, 8) = 1280 blocks
    dim3 block(NTHREADS);
    costvol_kernel<<<grid, block>>>(c1, warped, alpha, out);
}

// round 3
// speedup vs baseline: 2.6575x; 2.6575x over previous
#include <cuda_runtime.h>

// CostVolume: out[b, dy*9+dx, y, x] = leaky( mean_c( c1[b,c,y,x] * warped[b,c,y+dy-4,x+dx-4] ) )
// B=8, C=192, H=128, W=160, 81 offsets.
// Round 3: offsets split across blocks (5 dy-groups of 2), 2x2 pixels per thread,
// 72 register accumulators (fits, no spill), LDS.64 row loads shared across dy & y.

#define SR 4
#define C_TOTAL 192
#define H_TOTAL 128
#define W_TOTAL 160
#define B_TOTAL 8

#define TW 32        // tile width (pixels)
#define TH 16        // tile height (pixels)
#define NTHREADS 128 // 16 x-pairs * 8 y-pairs
#define CC 8         // channels per staged chunk
#define HW 40        // halo width  (TW + 2*SR)
#define HH 17        // halo rows needed for a 2-dy group over 16 rows
#define NGROUP 5     // dy groups: {0,1},{2,3},{4,5},{6,7},{8,(9 discarded)}

__global__ __launch_bounds__(NTHREADS, 4)
void costvol_kernel(const float* __restrict__ c1,
                    const float* __restrict__ warped,
                    const float* __restrict__ alpha,
                    float* __restrict__ out) {
    __shared__ __align__(16) float s_c1[CC][TH][TW];   // 16 KB
    __shared__ __align__(16) float s_w[CC][HH][HW];    // 21.25 KB

    const int tid = threadIdx.x;
    const int xp  = tid & 15;          // x-pair index
    const int yp  = tid >> 4;          // y-pair index 0..7
    const int tx0 = xp * 2;
    const int ry  = yp * 2;            // base pixel row within tile
    const int gid = blockIdx.x % NGROUP;
    const int x0  = (blockIdx.x / NGROUP) * TW;
    const int y0  = blockIdx.y * TH;
    const int b   = blockIdx.z;
    const int dyb = gid * 2;

    const float av = alpha[0];

    // acc[t][dx][y][x]: t = dy - dyb, 2x2 pixel block
    float acc[2][9][2][2];
    #pragma unroll
    for (int t = 0; t < 2; t++)
        #pragma unroll
        for (int d = 0; d < 9; d++) {
            acc[t][d][0][0] = 0.f; acc[t][d][0][1] = 0.f;
            acc[t][d][1][0] = 0.f; acc[t][d][1][1] = 0.f;
        }

    const size_t plane = (size_t)H_TOTAL * W_TOTAL;
    const float* c1b = c1     + (size_t)b * C_TOTAL * plane;
    const float* wb  = warped + (size_t)b * C_TOTAL * plane;

    #pragma unroll 1
    for (int cc = 0; cc < C_TOTAL; cc += CC) {
        // ---- stage c1 tile: CC*16*32 = 4096 floats = 1024 float4, 8/thread ----
        #pragma unroll
        for (int i = 0; i < 8; i++) {
            int idx = tid + i * NTHREADS;     // float4 slot
            int c   = idx >> 7;               // 128 float4 per channel
            int rem = idx & 127;
            int yy  = rem >> 3;
            int xx  = (rem & 7) * 4;
            *(float4*)&s_c1[c][yy][xx] =
                *(const float4*)(c1b + (size_t)(cc + c) * plane
                                 + (size_t)(y0 + yy) * W_TOTAL + (x0 + xx));
        }
        // ---- stage warped halo: per channel 17 rows x 10 float4 slots ----
        #pragma unroll
        for (int c = 0; c < CC; c++) {
            const float* wc = wb + (size_t)(cc + c) * plane;
            #pragma unroll
            for (int j = tid; j < HH * 10; j += NTHREADS) {  // 170 slots, 2 iters
                int row  = j / 10;
                int col  = j - row * 10;
                int gy   = y0 + dyb - SR + row;
                int gx0  = x0 - SR + col * 4;
                float4 v = make_float4(0.f, 0.f, 0.f, 0.f);
                if ((unsigned)gy < (unsigned)H_TOTAL) {
                    const float* src = wc + (size_t)gy * W_TOTAL + gx0;
                    if (gx0 >= 0 && gx0 + 3 < W_TOTAL) {
                        v = *(const float4*)src;
                    } else {
                        if ((unsigned)(gx0 + 0) < (unsigned)W_TOTAL) v.x = src[0];
                        if ((unsigned)(gx0 + 1) < (unsigned)W_TOTAL) v.y = src[1];
                        if ((unsigned)(gx0 + 2) < (unsigned)W_TOTAL) v.z = src[2];
                        if ((unsigned)(gx0 + 3) < (unsigned)W_TOTAL) v.w = src[3];
                    }
                }
                *(float4*)&s_w[c][row][col * 4] = v;
            }
        }
        __syncthreads();

        // ---- accumulate: 17 LDS.64 feed 72 FFMA per channel ----
        #pragma unroll 1
        for (int c = 0; c < CC; c++) {
            const float2 a0 = *(const float2*)&s_c1[c][ry][tx0];
            const float2 a1 = *(const float2*)&s_c1[c][ry + 1][tx0];
            // window row j = ry + s serves (y, t) pairs with y + t == s
            #pragma unroll
            for (int s = 0; s < 3; s++) {
                const float2* wr = (const float2*)&s_w[c][ry + s][tx0];
                float2 v0 = wr[0], v1 = wr[1], v2 = wr[2], v3 = wr[3], v4 = wr[4];
                float row[10] = {v0.x, v0.y, v1.x, v1.y, v2.x,
                                 v2.y, v3.x, v3.y, v4.x, v4.y};
                #pragma unroll
                for (int dx = 0; dx < 9; dx++) {
                    float wlo = row[dx], whi = row[dx + 1];
                    if (s < 2) {            // (y=0, t=s)
                        acc[s][dx][0][0] = fmaf(a0.x, wlo, acc[s][dx][0][0]);
                        acc[s][dx][0][1] = fmaf(a0.y, whi, acc[s][dx][0][1]);
                    }
                    if (s > 0) {            // (y=1, t=s-1)
                        acc[s - 1][dx][1][0] = fmaf(a1.x, wlo, acc[s - 1][dx][1][0]);
                        acc[s - 1][dx][1][1] = fmaf(a1.y, whi, acc[s - 1][dx][1][1]);
                    }
                }
            }
        }
        __syncthreads();
    }

    // ---- epilogue: mean, leaky-relu, float2 stores ----
    const float inv = 1.0f / (float)C_TOTAL;
    #pragma unroll
    for (int t = 0; t < 2; t++) {
        int dy = dyb + t;
        if (dy > 2 * SR) continue;          // group 4 discards dy=9
        #pragma unroll
        for (int dx = 0; dx < 9; dx++) {
            int o = dy * 9 + dx;
            #pragma unroll
            for (int y = 0; y < 2; y++) {
                float r0 = acc[t][dx][y][0] * inv;
                float r1 = acc[t][dx][y][1] * inv;
                float2 v;
                v.x = (r0 >= 0.f) ? r0 : av * r0;
                v.y = (r1 >= 0.f) ? r1 : av * r1;
                *(float2*)(out + (size_t)b * 81 * plane + (size_t)o * plane
                           + (size_t)(y0 + ry + y) * W_TOTAL + (x0 + tx0)) = v;
            }
        }
    }
}

extern "C" void kernel_launch(void* const* d_in, const int* in_sizes, int n_in,
                              void* d_out, int out_size) {
    const float* c1     = (const float*)d_in[0];
    const float* warped = (const float*)d_in[1];
    const float* alpha  = (const float*)d_in[2];
    float* out          = (float*)d_out;

    dim3 grid(NGROUP * (W_TOTAL / TW), H_TOTAL / TH, B_TOTAL);  // (25, 8, 8) = 1600
    dim3 block(NTHREADS);
    costvol_kernel<<<grid, block>>>(c1, warped, alpha, out);
}